// round 14
// baseline (speedup 1.0000x reference)
#include <cuda_runtime.h>

#define NN 64
#define CC 128
#define TT 2048
#define SS 9
#define CPB 16                  // output channels per block
#define ROWS (CPB + SS - 1)     // 24 staged rows
#define TTILE 256               // t per block
#define HALO 4
#define SMW (TTILE + 2 * HALO)  // 264 floats per smem row
#define THREADS 256
#define NSL 16                  // atomic slices
#define EPS 1e-5f

__device__ float g_psum[NSL][CC];
__device__ float g_psqs[NSL][CC];

__global__ __launch_bounds__(THREADS)
void conv_stats_kernel(const float* __restrict__ x,
                       const float* __restrict__ w,
                       float* __restrict__ out) {
    // grid: (CC/CPB=8, TT/TTILE=8, NN=64)
    const int c0 = blockIdx.x * CPB;
    const int t0 = blockIdx.y * TTILE;
    const int n  = blockIdx.z;
    const int tid = threadIdx.x;

    __shared__ float sx[ROWS][SMW];   // raw x rows, 25344 B
    __shared__ float ws[CPB][SS];     // weights, channel-edge zeroed

    // ---- weights -> smem; zero taps whose source channel is out of range ----
    if (tid < CPB * SS) {
        const int dcL = tid / SS;
        const int s   = tid - dcL * SS;
        const int ch  = c0 + dcL;
        const int src = ch - (SS / 2) + s;
        ws[dcL][s] = ((unsigned)src < (unsigned)CC) ? __ldg(&w[ch * SS + s]) : 0.0f;
    }

    const float* xb = x + (size_t)n * CC * TT;

    // ---- stage main region: rows 0..23, 64 aligned float4 per row, no predicates ----
    #pragma unroll
    for (int it = 0; it < (ROWS * (TTILE / 4)) / THREADS; it++) {   // 6 iters
        const int i = tid + it * THREADS;
        const int r = i >> 6;
        const int v = i & 63;
        const int cc = min(max(c0 - (SS / 2) + r, 0), CC - 1);      // clamp: real data,
                                                                     // zero weights kill it
        const float4 val = *reinterpret_cast<const float4*>(xb + cc * TT + t0 + 4 * v);
        *reinterpret_cast<float4*>(&sx[r][HALO + 4 * v]) = val;
    }
    // ---- halo: 2 aligned float4 per row, predicated at global time edges ----
    if (tid < ROWS * 2) {
        const int r    = tid >> 1;
        const int side = tid & 1;
        const int idx  = side ? (HALO + TTILE) : 0;       // smem col 260 or 0
        const int gt   = t0 - HALO + idx;                 // t0-4 or t0+256
        const int cc   = min(max(c0 - (SS / 2) + r, 0), CC - 1);
        float4 val = make_float4(0.f, 0.f, 0.f, 0.f);
        if (gt >= 0 && gt < TT)
            val = *reinterpret_cast<const float4*>(xb + cc * TT + gt);
        *reinterpret_cast<float4*>(&sx[r][idx]) = val;
    }
    __syncthreads();

    // ---- compute: thread -> 4 channels (d0..d0+3) x 4 times (q + 64m) ----
    const int d0 = (tid >> 6) * 4;     // local channel group
    const int q  = tid & 63;

    int shj[12];
    #pragma unroll
    for (int j = 0; j < 12; j++) {
        const int cc = min(max(c0 - (SS / 2) + d0 + j, 0), CC - 1);
        shj[j] = (cc % SS) - (SS / 2);
    }

    float acc[4][4];
    #pragma unroll
    for (int dc = 0; dc < 4; dc++)
        #pragma unroll
        for (int m = 0; m < 4; m++) acc[dc][m] = 0.0f;

    #pragma unroll
    for (int j = 0; j < 12; j++) {
        // xs[cc, t] = x[cc, t - sh]; smem col = HALO + (tloc - sh)
        const float* px = &sx[d0 + j][HALO + q - shj[j]];
        const float xv0 = px[0];
        const float xv1 = px[64];
        const float xv2 = px[128];
        const float xv3 = px[192];
        #pragma unroll
        for (int dc = 0; dc < 4; dc++) {
            const int s = j - dc;
            if (s >= 0 && s < SS) {
                const float wv = ws[d0 + dc][s];
                acc[dc][0] = fmaf(wv, xv0, acc[dc][0]);
                acc[dc][1] = fmaf(wv, xv1, acc[dc][1]);
                acc[dc][2] = fmaf(wv, xv2, acc[dc][2]);
                acc[dc][3] = fmaf(wv, xv3, acc[dc][3]);
            }
        }
    }

    // ---- store + per-channel stats ----
    float* ob = out + ((size_t)n * CC + c0 + d0) * TT + t0;
    float ssum[4], ssq[4];
    #pragma unroll
    for (int dc = 0; dc < 4; dc++) {
        ssum[dc] = 0.0f; ssq[dc] = 0.0f;
        #pragma unroll
        for (int m = 0; m < 4; m++) {
            const float a = acc[dc][m];
            ob[(size_t)dc * TT + q + 64 * m] = a;
            ssum[dc] += a;
            ssq[dc]   = fmaf(a, a, ssq[dc]);
        }
    }

    // warp-level reduce (channel group spans 2 warps -> 2 atomics per channel/block)
    const int lane = tid & 31;
    const int sl   = n & (NSL - 1);
    #pragma unroll
    for (int dc = 0; dc < 4; dc++) {
        float a = ssum[dc], b = ssq[dc];
        #pragma unroll
        for (int off = 16; off > 0; off >>= 1) {
            a += __shfl_xor_sync(0xFFFFFFFFu, a, off);
            b += __shfl_xor_sync(0xFFFFFFFFu, b, off);
        }
        if (lane == 0) {
            atomicAdd(&g_psum[sl][c0 + d0 + dc], a);
            atomicAdd(&g_psqs[sl][c0 + d0 + dc], b);
        }
    }
}

__global__ __launch_bounds__(512)
void normalize_kernel(float* __restrict__ out,
                      const float* __restrict__ gamma,
                      const float* __restrict__ beta) {
    // one block per (n, c) row; 512 threads x float4 = 2048 elements
    const int b = blockIdx.x;
    const int c = b & (CC - 1);
    float ms = 0.0f, vs = 0.0f;
    #pragma unroll
    for (int sl = 0; sl < NSL; sl++) {
        ms += g_psum[sl][c];
        vs += g_psqs[sl][c];
    }
    const float invM = 1.0f / (float)((size_t)NN * TT);
    float m  = ms * invM;
    float v  = vs * invM - m * m;
    float is = rsqrtf(v + EPS);
    float sc = __ldg(&gamma[c]) * is;
    float bi = __ldg(&beta[c]) - m * sc;

    float4* p = reinterpret_cast<float4*>(out + (size_t)b * TT);
    float4 v4 = p[threadIdx.x];
    v4.x = fmaxf(fmaf(v4.x, sc, bi), 0.0f);
    v4.y = fmaxf(fmaf(v4.y, sc, bi), 0.0f);
    v4.z = fmaxf(fmaf(v4.z, sc, bi), 0.0f);
    v4.w = fmaxf(fmaf(v4.w, sc, bi), 0.0f);
    p[threadIdx.x] = v4;
}

__global__ void zero_stats_kernel() {
    // runs LAST: leaves stats zeroed for the next graph replay
    // (__device__ globals are zero at module load, so replay 1 also sees zeros)
    for (int i = threadIdx.x; i < NSL * CC; i += 256) {
        (&g_psum[0][0])[i] = 0.0f;
        (&g_psqs[0][0])[i] = 0.0f;
    }
}

extern "C" void kernel_launch(void* const* d_in, const int* in_sizes, int n_in,
                              void* d_out, int out_size) {
    const float* x     = (const float*)d_in[0];   // (64,128,2048) f32
    const float* cw    = (const float*)d_in[1];   // (128,9)       f32
    const float* gamma = (const float*)d_in[2];   // (128,)        f32
    const float* beta  = (const float*)d_in[3];   // (128,)        f32
    float* out = (float*)d_out;                   // (64,128,2048) f32

    dim3 grid(CC / CPB, TT / TTILE, NN);          // (8, 8, 64) = 4096 blocks
    conv_stats_kernel<<<grid, THREADS>>>(x, cw, out);
    normalize_kernel<<<NN * CC, 512>>>(out, gamma, beta);
    zero_stats_kernel<<<1, 256>>>();
}